// round 5
// baseline (speedup 1.0000x reference)
#include <cuda_runtime.h>

// SymmetryControl (square-symmetry branch), B=16,C=96,H=96,W=96.
// Pair-orbit fused kernel:
//   Phase 1: linear coalesced LDG.128 of x,w; stage p = x*w and w in SMEM.
//   Phase 2: 3 threads per row; thread (ry, tx in 0..2) owns BOTH orbits
//            A = {tx+6k} and B = {(5-tx)+6k} (k=0..3) of its row, reads their
//            16 float4 from SMEM once, computes all 8 output float4 in regs.
// Output elem i = 4t+c:
//   shifts: f4 (t+18)%24, (t+12)%24, (t+6)%24, component c
//   flips:  f4 (5-t)%24 (slot (4-m)&3 in partner orbit) and (11-t)%24
//           (slot (1-m)&3), component 3-c (reversed)

#define W4    24
#define ROWS  32
#define NT    96
#define PITCH 30      // f4 pitch: (30*ry+pos)%8 == (tid%8) for own orbit -> conflict-free

__device__ __forceinline__ float4 orbit_out(
    const float4 p0, const float4 pa, const float4 pb, const float4 pc,
    const float4 w0, const float4 wa, const float4 wb, const float4 wc,
    const float4 qf, const float4 vf, const float4 qg, const float4 vg,
    float g0, float g1, float g2, float g3, float g4)
{
    float4 o;
    {   float a = p0.x;
        a = fmaf(g0, pa.x, a); a = fmaf(g1, pb.x, a); a = fmaf(g2, pc.x, a);
        a = fmaf(g3, qf.w, a); a = fmaf(g4, qg.w, a);
        float d = w0.x;
        d = fmaf(g0, wa.x, d); d = fmaf(g1, wb.x, d); d = fmaf(g2, wc.x, d);
        d = fmaf(g3, vf.w, d); d = fmaf(g4, vg.w, d);
        o.x = __fdividef(a, d); }
    {   float a = p0.y;
        a = fmaf(g0, pa.y, a); a = fmaf(g1, pb.y, a); a = fmaf(g2, pc.y, a);
        a = fmaf(g3, qf.z, a); a = fmaf(g4, qg.z, a);
        float d = w0.y;
        d = fmaf(g0, wa.y, d); d = fmaf(g1, wb.y, d); d = fmaf(g2, wc.y, d);
        d = fmaf(g3, vf.z, d); d = fmaf(g4, vg.z, d);
        o.y = __fdividef(a, d); }
    {   float a = p0.z;
        a = fmaf(g0, pa.z, a); a = fmaf(g1, pb.z, a); a = fmaf(g2, pc.z, a);
        a = fmaf(g3, qf.y, a); a = fmaf(g4, qg.y, a);
        float d = w0.z;
        d = fmaf(g0, wa.z, d); d = fmaf(g1, wb.z, d); d = fmaf(g2, wc.z, d);
        d = fmaf(g3, vf.y, d); d = fmaf(g4, vg.y, d);
        o.z = __fdividef(a, d); }
    {   float a = p0.w;
        a = fmaf(g0, pa.w, a); a = fmaf(g1, pb.w, a); a = fmaf(g2, pc.w, a);
        a = fmaf(g3, qf.x, a); a = fmaf(g4, qg.x, a);
        float d = w0.w;
        d = fmaf(g0, wa.w, d); d = fmaf(g1, wb.w, d); d = fmaf(g2, wc.w, d);
        d = fmaf(g3, vf.x, d); d = fmaf(g4, vg.x, d);
        o.w = __fdividef(a, d); }
    return o;
}

__global__ __launch_bounds__(NT)
void symmetry_control_pair(const float4* __restrict__ x4,
                           const float*  __restrict__ s,
                           const float4* __restrict__ w4,
                           float4* __restrict__ out4,
                           int rows_per_batch /* C*H = 9216 */)
{
    __shared__ float4 sp[ROWS][PITCH];   // p = x*w
    __shared__ float4 sv[ROWS][PITCH];   // w
    __shared__ float  sg[5];

    const int tid = threadIdx.x;
    const size_t blk_f4 = (size_t)blockIdx.x * (ROWS * W4);   // 768 f4 / block

    // ---- Phase 1: coalesced load + stage (16 LDG.128 per thread) ----------
    {
        const int col  = tid % W4;       // constant over j (96 = 4*24)
        const int row0 = tid / W4;       // 0..3
#pragma unroll
        for (int j = 0; j < 8; j++) {
            const int idx = tid + NT * j;
            const int row = row0 + 4 * j;
            const float4 xv = x4[blk_f4 + idx];
            const float4 wv = w4[blk_f4 + idx];
            sp[row][col] = make_float4(xv.x * wv.x, xv.y * wv.y,
                                       xv.z * wv.z, xv.w * wv.w);
            sv[row][col] = wv;
        }
    }

    if (tid < 5) {
        const int b = (int)(((long long)blockIdx.x * ROWS) / rows_per_batch);
        const float svv = s[b * 5 + tid];
        sg[tid] = 1.0f / (1.0f + __expf(-svv));
    }
    __syncthreads();

    // ---- Phase 2: pair-orbit compute, 8 output f4 per thread ---------------
    const int tx = tid % 3;              // orbit A id (0..2)
    const int ry = tid / 3;              // row within block (0..31)
    const int sx = 5 - tx;               // orbit B id (3..5)

    const float g0 = sg[0], g1 = sg[1], g2 = sg[2], g3 = sg[3], g4 = sg[4];

    float4 PA[4], WA[4], PB[4], WB[4];
#pragma unroll
    for (int k = 0; k < 4; k++) {
        PA[k] = sp[ry][tx + 6 * k];
        WA[k] = sv[ry][tx + 6 * k];
        PB[k] = sp[ry][sx + 6 * k];
        WB[k] = sv[ry][sx + 6 * k];
    }

    const size_t rowbase = blk_f4 + (size_t)ry * W4;

#pragma unroll
    for (int m = 0; m < 4; m++) {
        const int m1 = (m + 1) & 3;      // +6  f4 (270deg)
        const int m2 = (m + 2) & 3;      // +12 f4 (180deg)
        const int m3 = (m + 3) & 3;      // +18 f4 (90deg)
        const int kf90  = (4 - m) & 3;   // flip90  slot in partner orbit
        const int kf180 = (1 - m) & 3;   // flip180 slot in partner orbit

        // output at orbit A position tx+6m (flips from orbit B)
        const float4 oA = orbit_out(PA[m], PA[m3], PA[m2], PA[m1],
                                    WA[m], WA[m3], WA[m2], WA[m1],
                                    PB[kf90], WB[kf90], PB[kf180], WB[kf180],
                                    g0, g1, g2, g3, g4);
        // output at orbit B position (5-tx)+6m (flips from orbit A)
        const float4 oB = orbit_out(PB[m], PB[m3], PB[m2], PB[m1],
                                    WB[m], WB[m3], WB[m2], WB[m1],
                                    PA[kf90], WA[kf90], PA[kf180], WA[kf180],
                                    g0, g1, g2, g3, g4);

        out4[rowbase + tx + 6 * m] = oA;
        out4[rowbase + sx + 6 * m] = oB;
    }
}

extern "C" void kernel_launch(void* const* d_in, const int* in_sizes, int n_in,
                              void* d_out, int out_size)
{
    const float4* x4 = (const float4*)d_in[0];
    const float*  s  = (const float*)d_in[1];
    const float4* w4 = (const float4*)d_in[2];
    float4* out4 = (float4*)d_out;

    const long long total = in_sizes[0];          // B*C*H*W
    const int B = in_sizes[1] / 5;                // 16
    const long long rows = total / 96;            // B*C*H = 147456
    const int rows_per_batch = (int)(rows / B);   // 9216

    const long long nblocks = rows / ROWS;        // 4608
    symmetry_control_pair<<<(unsigned)nblocks, NT>>>(x4, s, w4, out4, rows_per_batch);
}

// round 6
// speedup vs baseline: 1.0524x; 1.0524x over previous
#include <cuda_runtime.h>

// SymmetryControl (square-symmetry branch), B=16,C=96,H=96,W=96.
// Barrier-free pair-orbit kernel: one thread per (row, tx in 0..2) owns BOTH
// orbits A={tx+6k} and B={(5-tx)+6k} (k=0..3, float4 units) of its row.
// It loads its 16 float4 of x and w directly from GMEM (no SMEM, no barrier),
// computes all 8 output float4, and stores them. Every 128B line a warp
// touches is fully consumed within that warp (3 threads/row cover 0..5 +6k).
//
// Output elem i = 4t+c:
//   shifts: f4 (t+18)%24, (t+12)%24, (t+6)%24, component c
//   flips:  f4 (5-t)%24 (slot (4-m)&3 of partner orbit) and (11-t)%24
//           (slot (1-m)&3), component 3-c (reversed)

#define W4 24
#define NT 256

__device__ __forceinline__ float4 orbit_out(
    const float4 p0, const float4 pa, const float4 pb, const float4 pc,
    const float4 w0, const float4 wa, const float4 wb, const float4 wc,
    const float4 qf, const float4 vf, const float4 qg, const float4 vg,
    float g0, float g1, float g2, float g3, float g4)
{
    float4 o;
    {   float a = p0.x;
        a = fmaf(g0, pa.x, a); a = fmaf(g1, pb.x, a); a = fmaf(g2, pc.x, a);
        a = fmaf(g3, qf.w, a); a = fmaf(g4, qg.w, a);
        float d = w0.x;
        d = fmaf(g0, wa.x, d); d = fmaf(g1, wb.x, d); d = fmaf(g2, wc.x, d);
        d = fmaf(g3, vf.w, d); d = fmaf(g4, vg.w, d);
        o.x = __fdividef(a, d); }
    {   float a = p0.y;
        a = fmaf(g0, pa.y, a); a = fmaf(g1, pb.y, a); a = fmaf(g2, pc.y, a);
        a = fmaf(g3, qf.z, a); a = fmaf(g4, qg.z, a);
        float d = w0.y;
        d = fmaf(g0, wa.y, d); d = fmaf(g1, wb.y, d); d = fmaf(g2, wc.y, d);
        d = fmaf(g3, vf.z, d); d = fmaf(g4, vg.z, d);
        o.y = __fdividef(a, d); }
    {   float a = p0.z;
        a = fmaf(g0, pa.z, a); a = fmaf(g1, pb.z, a); a = fmaf(g2, pc.z, a);
        a = fmaf(g3, qf.y, a); a = fmaf(g4, qg.y, a);
        float d = w0.z;
        d = fmaf(g0, wa.z, d); d = fmaf(g1, wb.z, d); d = fmaf(g2, wc.z, d);
        d = fmaf(g3, vf.y, d); d = fmaf(g4, vg.y, d);
        o.z = __fdividef(a, d); }
    {   float a = p0.w;
        a = fmaf(g0, pa.w, a); a = fmaf(g1, pb.w, a); a = fmaf(g2, pc.w, a);
        a = fmaf(g3, qf.x, a); a = fmaf(g4, qg.x, a);
        float d = w0.w;
        d = fmaf(g0, wa.w, d); d = fmaf(g1, wb.w, d); d = fmaf(g2, wc.w, d);
        d = fmaf(g3, vf.x, d); d = fmaf(g4, vg.x, d);
        o.w = __fdividef(a, d); }
    return o;
}

__global__ __launch_bounds__(NT)
void symmetry_control_nb(const float4* __restrict__ x4,
                         const float*  __restrict__ s,
                         const float4* __restrict__ w4,
                         float4* __restrict__ out4,
                         int rows_per_batch /* C*H = 9216 */)
{
    const int gtid = blockIdx.x * NT + threadIdx.x;
    const int tx  = gtid % 3;            // orbit A id (0..2)
    const int row = gtid / 3;            // global row
    const int sx  = 5 - tx;              // orbit B id (3..5)
    const size_t base = (size_t)row * W4;

    // Load both orbits of x and w (16 independent LDG.128, front-batched).
    float4 PA[4], WA[4], PB[4], WB[4];
#pragma unroll
    for (int k = 0; k < 4; k++) {
        const float4 xa = x4[base + tx + 6 * k];
        const float4 xb = x4[base + sx + 6 * k];
        WA[k] = w4[base + tx + 6 * k];
        WB[k] = w4[base + sx + 6 * k];
        PA[k] = make_float4(xa.x * WA[k].x, xa.y * WA[k].y,
                            xa.z * WA[k].z, xa.w * WA[k].w);
        PB[k] = make_float4(xb.x * WB[k].x, xb.y * WB[k].y,
                            xb.z * WB[k].z, xb.w * WB[k].w);
    }

    // Sigmoid gates: 5 scalar loads per thread; same batch across a warp ->
    // broadcast from L1. MUFU cost negligible.
    const int b = row / rows_per_batch;
    const float g0 = 1.0f / (1.0f + __expf(-__ldg(&s[b * 5 + 0])));
    const float g1 = 1.0f / (1.0f + __expf(-__ldg(&s[b * 5 + 1])));
    const float g2 = 1.0f / (1.0f + __expf(-__ldg(&s[b * 5 + 2])));
    const float g3 = 1.0f / (1.0f + __expf(-__ldg(&s[b * 5 + 3])));
    const float g4 = 1.0f / (1.0f + __expf(-__ldg(&s[b * 5 + 4])));

#pragma unroll
    for (int m = 0; m < 4; m++) {
        const int m1 = (m + 1) & 3;      // +6  f4 (270deg)
        const int m2 = (m + 2) & 3;      // +12 f4 (180deg)
        const int m3 = (m + 3) & 3;      // +18 f4 (90deg)
        const int kf90  = (4 - m) & 3;   // flip90  slot in partner orbit
        const int kf180 = (1 - m) & 3;   // flip180 slot in partner orbit

        const float4 oA = orbit_out(PA[m], PA[m3], PA[m2], PA[m1],
                                    WA[m], WA[m3], WA[m2], WA[m1],
                                    PB[kf90], WB[kf90], PB[kf180], WB[kf180],
                                    g0, g1, g2, g3, g4);
        const float4 oB = orbit_out(PB[m], PB[m3], PB[m2], PB[m1],
                                    WB[m], WB[m3], WB[m2], WB[m1],
                                    PA[kf90], WA[kf90], PA[kf180], WA[kf180],
                                    g0, g1, g2, g3, g4);

        out4[base + tx + 6 * m] = oA;
        out4[base + sx + 6 * m] = oB;
    }
}

extern "C" void kernel_launch(void* const* d_in, const int* in_sizes, int n_in,
                              void* d_out, int out_size)
{
    const float4* x4 = (const float4*)d_in[0];
    const float*  s  = (const float*)d_in[1];
    const float4* w4 = (const float4*)d_in[2];
    float4* out4 = (float4*)d_out;

    const long long total = in_sizes[0];          // B*C*H*W = 14,155,776
    const int B = in_sizes[1] / 5;                // 16
    const long long rows = total / 96;            // B*C*H = 147,456
    const int rows_per_batch = (int)(rows / B);   // 9216

    const long long nthreads = rows * 3;          // 442,368
    const long long nblocks  = nthreads / NT;     // 1728 (exact)
    symmetry_control_nb<<<(unsigned)nblocks, NT>>>(x4, s, w4, out4, rows_per_batch);
}

// round 7
// speedup vs baseline: 1.1323x; 1.0759x over previous
#include <cuda_runtime.h>

// SymmetryControl (square-symmetry branch), B=16,C=96,H=96,W=96.
// Barrier-free pair-orbit kernel, occupancy-tuned:
//  - 128-thread blocks, __launch_bounds__(128,5) -> 5 blocks/SM (640 thr, reg cap 102)
//  - streaming ld.cs / st.cs (zero-reuse workload)
// Thread (row, tx in 0..2) owns orbits A={tx+6k}, B={(5-tx)+6k} (k=0..3, f4
// units) of its 24-f4 row; loads its 16 f4 directly, computes 8 output f4.
// Output elem i = 4t+c:
//   shifts: f4 (t+18)%24, (t+12)%24, (t+6)%24, component c
//   flips:  f4 (5-t)%24 (slot (4-m)&3 of partner orbit) and (11-t)%24
//           (slot (1-m)&3), component 3-c (reversed)

#define W4 24
#define NT 128

__device__ __forceinline__ float4 ldcs4(const float4* p) {
#if __CUDA_ARCH__ >= 320
    return __ldcs(p);
#else
    return *p;
#endif
}

__device__ __forceinline__ float4 orbit_out(
    const float4 p0, const float4 pa, const float4 pb, const float4 pc,
    const float4 w0, const float4 wa, const float4 wb, const float4 wc,
    const float4 qf, const float4 vf, const float4 qg, const float4 vg,
    float g0, float g1, float g2, float g3, float g4)
{
    float4 o;
    {   float a = p0.x;
        a = fmaf(g0, pa.x, a); a = fmaf(g1, pb.x, a); a = fmaf(g2, pc.x, a);
        a = fmaf(g3, qf.w, a); a = fmaf(g4, qg.w, a);
        float d = w0.x;
        d = fmaf(g0, wa.x, d); d = fmaf(g1, wb.x, d); d = fmaf(g2, wc.x, d);
        d = fmaf(g3, vf.w, d); d = fmaf(g4, vg.w, d);
        o.x = __fdividef(a, d); }
    {   float a = p0.y;
        a = fmaf(g0, pa.y, a); a = fmaf(g1, pb.y, a); a = fmaf(g2, pc.y, a);
        a = fmaf(g3, qf.z, a); a = fmaf(g4, qg.z, a);
        float d = w0.y;
        d = fmaf(g0, wa.y, d); d = fmaf(g1, wb.y, d); d = fmaf(g2, wc.y, d);
        d = fmaf(g3, vf.z, d); d = fmaf(g4, vg.z, d);
        o.y = __fdividef(a, d); }
    {   float a = p0.z;
        a = fmaf(g0, pa.z, a); a = fmaf(g1, pb.z, a); a = fmaf(g2, pc.z, a);
        a = fmaf(g3, qf.y, a); a = fmaf(g4, qg.y, a);
        float d = w0.z;
        d = fmaf(g0, wa.z, d); d = fmaf(g1, wb.z, d); d = fmaf(g2, wc.z, d);
        d = fmaf(g3, vf.y, d); d = fmaf(g4, vg.y, d);
        o.z = __fdividef(a, d); }
    {   float a = p0.w;
        a = fmaf(g0, pa.w, a); a = fmaf(g1, pb.w, a); a = fmaf(g2, pc.w, a);
        a = fmaf(g3, qf.x, a); a = fmaf(g4, qg.x, a);
        float d = w0.w;
        d = fmaf(g0, wa.w, d); d = fmaf(g1, wb.w, d); d = fmaf(g2, wc.w, d);
        d = fmaf(g3, vf.x, d); d = fmaf(g4, vg.x, d);
        o.w = __fdividef(a, d); }
    return o;
}

__global__ __launch_bounds__(NT, 5)
void symmetry_control_occ(const float4* __restrict__ x4,
                          const float*  __restrict__ s,
                          const float4* __restrict__ w4,
                          float4* __restrict__ out4,
                          int rows_per_batch /* C*H = 9216 */)
{
    const int gtid = blockIdx.x * NT + threadIdx.x;
    const int tx  = gtid % 3;            // orbit A id (0..2)
    const int row = gtid / 3;            // global row
    const int sx  = 5 - tx;              // orbit B id (3..5)
    const size_t base = (size_t)row * W4;

    // Gates first: their latency hides under the bulk loads below.
    const int b = row / rows_per_batch;
    const float g0 = 1.0f / (1.0f + __expf(-s[b * 5 + 0]));
    const float g1 = 1.0f / (1.0f + __expf(-s[b * 5 + 1]));
    const float g2 = 1.0f / (1.0f + __expf(-s[b * 5 + 2]));
    const float g3 = 1.0f / (1.0f + __expf(-s[b * 5 + 3]));
    const float g4 = 1.0f / (1.0f + __expf(-s[b * 5 + 4]));

    // 16 independent streaming LDG.128, front-batched.
    float4 PA[4], WA[4], PB[4], WB[4];
#pragma unroll
    for (int k = 0; k < 4; k++) {
        const float4 xa = ldcs4(&x4[base + tx + 6 * k]);
        const float4 xb = ldcs4(&x4[base + sx + 6 * k]);
        WA[k] = ldcs4(&w4[base + tx + 6 * k]);
        WB[k] = ldcs4(&w4[base + sx + 6 * k]);
        PA[k] = make_float4(xa.x * WA[k].x, xa.y * WA[k].y,
                            xa.z * WA[k].z, xa.w * WA[k].w);
        PB[k] = make_float4(xb.x * WB[k].x, xb.y * WB[k].y,
                            xb.z * WB[k].z, xb.w * WB[k].w);
    }

#pragma unroll
    for (int m = 0; m < 4; m++) {
        const int m1 = (m + 1) & 3;      // +6  f4 (270deg)
        const int m2 = (m + 2) & 3;      // +12 f4 (180deg)
        const int m3 = (m + 3) & 3;      // +18 f4 (90deg)
        const int kf90  = (4 - m) & 3;   // flip90  slot in partner orbit
        const int kf180 = (1 - m) & 3;   // flip180 slot in partner orbit

        const float4 oA = orbit_out(PA[m], PA[m3], PA[m2], PA[m1],
                                    WA[m], WA[m3], WA[m2], WA[m1],
                                    PB[kf90], WB[kf90], PB[kf180], WB[kf180],
                                    g0, g1, g2, g3, g4);
        const float4 oB = orbit_out(PB[m], PB[m3], PB[m2], PB[m1],
                                    WB[m], WB[m3], WB[m2], WB[m1],
                                    PA[kf90], WA[kf90], PA[kf180], WA[kf180],
                                    g0, g1, g2, g3, g4);

        __stcs(&out4[base + tx + 6 * m], oA);
        __stcs(&out4[base + sx + 6 * m], oB);
    }
}

extern "C" void kernel_launch(void* const* d_in, const int* in_sizes, int n_in,
                              void* d_out, int out_size)
{
    const float4* x4 = (const float4*)d_in[0];
    const float*  s  = (const float*)d_in[1];
    const float4* w4 = (const float4*)d_in[2];
    float4* out4 = (float4*)d_out;

    const long long total = in_sizes[0];          // B*C*H*W = 14,155,776
    const int B = in_sizes[1] / 5;                // 16
    const long long rows = total / 96;            // B*C*H = 147,456
    const int rows_per_batch = (int)(rows / B);   // 9216

    const long long nthreads = rows * 3;          // 442,368
    const long long nblocks  = nthreads / NT;     // 3456 (exact)
    symmetry_control_occ<<<(unsigned)nblocks, NT>>>(x4, s, w4, out4, rows_per_batch);
}